// round 9
// baseline (speedup 1.0000x reference)
#include <cuda_runtime.h>
#include <cstdint>

// Shapes (fixed per reference): B=4, N=256, XDIM=256, EDIM=128, H=8, DF=32
#define NB 4
#define NN 256
#define CC 256   // XDIM
#define EE 128   // EDIM
#define SCALE 0.17677669529663687f  // 1/sqrt(32)

#define NEWX_ELEMS (NB*NN*CC)       // 262144 floats, then newE follows

// ---------------- scratch (device globals; no allocation allowed) -----------
__device__ __align__(16) float g_Qs[NB*NN*CC];   // Q*(1/sqrt(DF)) [row][c]
__device__ __align__(16) float g_Kt[NB*CC*NN];   // K transposed [b][c][j]
__device__ __align__(16) float g_W2[384*128];    // [Weo(256x128); Wea@Weo(128x128)]
__device__ __align__(16) float g_bem1[256];      // bem + 1
__device__ __align__(16) float g_beo2[128];      // beo + bea@Weo

// ---------------- f32x2 packed-FMA helpers ----------------------------------
__device__ __forceinline__ unsigned long long pk2(float lo, float hi) {
    unsigned long long r;
    asm("mov.b64 %0, {%1,%2};" : "=l"(r) : "f"(lo), "f"(hi));
    return r;
}
__device__ __forceinline__ void upk2(unsigned long long v, float& lo, float& hi) {
    asm("mov.b64 {%0,%1}, %2;" : "=f"(lo), "=f"(hi) : "l"(v));
}
__device__ __forceinline__ void ffma2(unsigned long long& d,
                                      unsigned long long a, unsigned long long b) {
    asm("fma.rn.f32x2 %0, %1, %2, %0;" : "+l"(d) : "l"(a), "l"(b));
}

// ---------------- P0: tiny precompute ----------------------------------------
// blocks 0..255  : copy Weo row into g_W2
// blocks 256..383: g_W2 row 256+d = Wea[d,:] @ Weo
// block 384      : g_beo2 = beo + bea @ Weo
// block 385      : g_bem1 = bem + 1
__global__ void p0_kernel(const float* __restrict__ Wea,
                          const float* __restrict__ Weo,
                          const float* __restrict__ beo,
                          const float* __restrict__ bea,
                          const float* __restrict__ bem) {
    int blk = blockIdx.x, tid = threadIdx.x;
    if (blk < 256) {
        if (tid < 128) g_W2[blk*128 + tid] = Weo[blk*128 + tid];
    } else if (blk < 384) {
        int d = blk - 256;
        if (tid < 128) {
            float s = 0.f;
            for (int c = 0; c < 256; c++) s += Wea[d*256 + c] * Weo[c*128 + tid];
            g_W2[(256 + d)*128 + tid] = s;
        }
    } else if (blk == 384) {
        if (tid < 128) {
            float s = beo[tid];
            for (int c = 0; c < 256; c++) s += bea[c] * Weo[c*128 + tid];
            g_beo2[tid] = s;
        }
    } else {
        if (tid < 256) g_bem1[tid] = bem[tid] + 1.0f;
    }
}

// ---------------- P1: node projections + newX --------------------------------
// Qs = (x@Wq+bq)*scale ; Kt[b][c][j] = (x@Wk+bk) ; newX = ((x@Wv+bv)@Wxo)+bxo
// 64 CTAs, 16 node-rows each, 256 threads (one output column per thread).
__global__ __launch_bounds__(256) void p1_kernel(
    const float* __restrict__ x,
    const float* __restrict__ Wq, const float* __restrict__ bq,
    const float* __restrict__ Wk, const float* __restrict__ bk,
    const float* __restrict__ Wv, const float* __restrict__ bv,
    const float* __restrict__ Wxo, const float* __restrict__ bxo,
    float* __restrict__ outX) {
    __shared__ float xs[16][256];
    __shared__ float vs[16][256];
    int blk = blockIdx.x, tid = threadIdx.x;

    const float* xg = x + (size_t)blk * 16 * 256;
    for (int idx = tid; idx < 4096; idx += 256) xs[idx >> 8][idx & 255] = xg[idx];
    __syncthreads();

    int c = tid;
    float aq[16], ak[16], av[16];
#pragma unroll
    for (int r = 0; r < 16; r++) { aq[r] = 0.f; ak[r] = 0.f; av[r] = 0.f; }
    for (int k = 0; k < 256; k++) {
        float wq = Wq[k*256 + c], wk = Wk[k*256 + c], wv = Wv[k*256 + c];
#pragma unroll
        for (int r = 0; r < 16; r++) {
            float a = xs[r][k];
            aq[r] += a * wq; ak[r] += a * wk; av[r] += a * wv;
        }
    }
    float bqv = bq[c], bkv = bk[c], bvv = bv[c];
#pragma unroll
    for (int r = 0; r < 16; r++) {
        int row = blk*16 + r;
        g_Qs[row*256 + c] = (aq[r] + bqv) * SCALE;
        int b = row >> 8, j = row & 255;
        g_Kt[(b*256 + c)*256 + j] = ak[r] + bkv;   // transposed store
        vs[r][c] = av[r] + bvv;
    }
    __syncthreads();

    // newX = V @ Wxo + bxo   (softmax collapses: weighted_V == V exactly)
#pragma unroll
    for (int r = 0; r < 16; r++) aq[r] = 0.f;
    for (int k = 0; k < 256; k++) {
        float w = Wxo[k*256 + c];
#pragma unroll
        for (int r = 0; r < 16; r++) aq[r] += vs[r][k] * w;
    }
    float bx = bxo[c];
#pragma unroll
    for (int r = 0; r < 16; r++) outX[(blk*16 + r)*256 + c] = aq[r] + bx;
}

// ---------------- K2: fused edge kernel --------------------------------------
// Per CTA: fixed (b,i), 64 j-rows.
//   GEMM1: T[64x256] = e_tile @ Wem + (bem+1)
//   elementwise: Y = Qs_i (.) K_j (.) T
//   GEMM2: out[64x128] = [Y | e_tile](64x384) @ g_W2(384x128) + beo2
// SMEM: et[128][68] (e transposed) + Tt[256][68] (Y transposed) + Bb staging.
#define ET_STRIDE 68
#define SM_FLOATS (128*ET_STRIDE + 256*ET_STRIDE + 8192 + 256)   // 34560

__global__ __launch_bounds__(256, 1) void k2_kernel(
    const float* __restrict__ e, const float* __restrict__ Wem,
    float* __restrict__ out) {
    extern __shared__ float sm[];
    float* et = sm;                       // [128][68]
    float* Tt = sm + 128*ET_STRIDE;       // [256][68]
    float* Bb = Tt + 256*ET_STRIDE;       // [8192] weight staging
    float* qs = Bb + 8192;                // [256]

    int tid = threadIdx.x;
    int blk = blockIdx.x;
    int bi = blk >> 2;           // b*256 + i
    int jt = blk & 3;
    int b  = bi >> 8;
    int j0 = jt * 64;

    // load e tile (contiguous 32KB) transposed into smem: et[k][r]
    const float* eg = e + (size_t)(bi*256 + j0) * 128;
    for (int idx = tid; idx < 8192; idx += 256) {
        int r = idx >> 7, k = idx & 127;
        et[k*ET_STRIDE + r] = eg[idx];
    }
    qs[tid] = g_Qs[bi*256 + tid];
    __syncthreads();

    // ---------- GEMM1: 64x256 = et(64x128 k) @ Wem, FFMA2 col-pairs ----------
    int rg = tid & 15, cg = tid >> 4;
    int r0 = rg * 4, c0 = cg * 16;
    unsigned long long acc[4][8];
#pragma unroll
    for (int p = 0; p < 8; p++) {
        unsigned long long init = pk2(g_bem1[c0 + 2*p], g_bem1[c0 + 2*p + 1]);
#pragma unroll
        for (int r = 0; r < 4; r++) acc[r][p] = init;
    }
    for (int kk = 0; kk < 128; kk += 32) {
        const float4* src = (const float4*)(Wem + kk*256);
        float4* dst = (float4*)Bb;
        for (int i4 = tid; i4 < 2048; i4 += 256) dst[i4] = src[i4];
        __syncthreads();
#pragma unroll 4
        for (int k = 0; k < 32; k++) {
            float4 a4 = *(const float4*)(et + (kk + k)*ET_STRIDE + r0);
            unsigned long long a0 = pk2(a4.x, a4.x), a1 = pk2(a4.y, a4.y),
                               a2 = pk2(a4.z, a4.z), a3 = pk2(a4.w, a4.w);
            const ulonglong2* br = (const ulonglong2*)(Bb + k*256 + c0);
            ulonglong2 q0 = br[0], q1 = br[1], q2 = br[2], q3 = br[3];
            unsigned long long bp[8] = {q0.x, q0.y, q1.x, q1.y, q2.x, q2.y, q3.x, q3.y};
#pragma unroll
            for (int p = 0; p < 8; p++) {
                ffma2(acc[0][p], a0, bp[p]);
                ffma2(acc[1][p], a1, bp[p]);
                ffma2(acc[2][p], a2, bp[p]);
                ffma2(acc[3][p], a3, bp[p]);
            }
        }
        __syncthreads();
    }

    // ---------- elementwise: Y = T * qs[c] * K[b][j][c], store Tt[c][r] ------
    const float* Kb = g_Kt + b * 65536;
#pragma unroll
    for (int p = 0; p < 8; p++) {
        int c = c0 + 2*p;
        float4 k0 = *(const float4*)(Kb + c*256 + j0 + r0);
        float4 k1 = *(const float4*)(Kb + (c + 1)*256 + j0 + r0);
        float q0 = qs[c], q1 = qs[c + 1];
        float y0[4], y1[4];
#pragma unroll
        for (int r = 0; r < 4; r++) {
            float lo, hi; upk2(acc[r][p], lo, hi);
            y0[r] = lo * q0; y1[r] = hi * q1;
        }
        y0[0] *= k0.x; y0[1] *= k0.y; y0[2] *= k0.z; y0[3] *= k0.w;
        y1[0] *= k1.x; y1[1] *= k1.y; y1[2] *= k1.z; y1[3] *= k1.w;
        *(float4*)(Tt + c*ET_STRIDE + r0)       = make_float4(y0[0], y0[1], y0[2], y0[3]);
        *(float4*)(Tt + (c + 1)*ET_STRIDE + r0) = make_float4(y1[0], y1[1], y1[2], y1[3]);
    }
    __syncthreads();

    // ---------- GEMM2: 64x128 = [Y | e](64x384 k) @ g_W2 + beo2 --------------
    int c0b = cg * 8;   // 16 col-groups x 8 cols = 128
    unsigned long long acc2[4][4];
#pragma unroll
    for (int p = 0; p < 4; p++) {
        unsigned long long init = pk2(g_beo2[c0b + 2*p], g_beo2[c0b + 2*p + 1]);
#pragma unroll
        for (int r = 0; r < 4; r++) acc2[r][p] = init;
    }
    for (int ch = 0; ch < 6; ch++) {
        const float4* src = (const float4*)(g_W2 + ch*64*128);
        float4* dst = (float4*)Bb;
        for (int i4 = tid; i4 < 2048; i4 += 256) dst[i4] = src[i4];
        __syncthreads();
        const float* Abase = (ch < 4) ? (Tt + ch*64*ET_STRIDE)
                                      : (et + (ch - 4)*64*ET_STRIDE);
#pragma unroll 4
        for (int k = 0; k < 64; k++) {
            float4 a4 = *(const float4*)(Abase + k*ET_STRIDE + r0);
            unsigned long long a0 = pk2(a4.x, a4.x), a1 = pk2(a4.y, a4.y),
                               a2 = pk2(a4.z, a4.z), a3 = pk2(a4.w, a4.w);
            const ulonglong2* br = (const ulonglong2*)(Bb + k*128 + c0b);
            ulonglong2 q0 = br[0], q1 = br[1];
            unsigned long long bp[4] = {q0.x, q0.y, q1.x, q1.y};
#pragma unroll
            for (int p = 0; p < 4; p++) {
                ffma2(acc2[0][p], a0, bp[p]);
                ffma2(acc2[1][p], a1, bp[p]);
                ffma2(acc2[2][p], a2, bp[p]);
                ffma2(acc2[3][p], a3, bp[p]);
            }
        }
        __syncthreads();
    }

    // ---------- store newE tile ----------------------------------------------
    float* outE = out + NEWX_ELEMS;
#pragma unroll
    for (int r = 0; r < 4; r++) {
        size_t row = (size_t)(bi*256 + j0 + r0 + r);
        float f[8];
#pragma unroll
        for (int p = 0; p < 4; p++) upk2(acc2[r][p], f[2*p], f[2*p + 1]);
        *(float4*)(outE + row*128 + c0b)     = make_float4(f[0], f[1], f[2], f[3]);
        *(float4*)(outE + row*128 + c0b + 4) = make_float4(f[4], f[5], f[6], f[7]);
    }
}

// ---------------- launch ------------------------------------------------------
extern "C" void kernel_launch(void* const* d_in, const int* in_sizes, int n_in,
                              void* d_out, int out_size) {
    const float* x   = (const float*)d_in[0];
    const float* e   = (const float*)d_in[1];
    const float* Wq  = (const float*)d_in[2];
    const float* bq  = (const float*)d_in[3];
    const float* Wk  = (const float*)d_in[4];
    const float* bk  = (const float*)d_in[5];
    const float* Wv  = (const float*)d_in[6];
    const float* bv  = (const float*)d_in[7];
    const float* Wem = (const float*)d_in[8];
    const float* bem = (const float*)d_in[9];
    const float* Wea = (const float*)d_in[10];
    const float* bea = (const float*)d_in[11];
    const float* Wxo = (const float*)d_in[12];
    const float* bxo = (const float*)d_in[13];
    const float* Weo = (const float*)d_in[14];
    const float* beo = (const float*)d_in[15];
    float* out = (float*)d_out;

    cudaFuncSetAttribute(k2_kernel, cudaFuncAttributeMaxDynamicSharedMemorySize,
                         SM_FLOATS * (int)sizeof(float));

    p0_kernel<<<386, 256>>>(Wea, Weo, beo, bea, bem);
    p1_kernel<<<64, 256>>>(x, Wq, bq, Wk, bk, Wv, bv, Wxo, bxo, out);
    k2_kernel<<<4096, 256, SM_FLOATS * (int)sizeof(float)>>>(e, Wem, out);
}

// round 12
// speedup vs baseline: 1.2924x; 1.2924x over previous
#include <cuda_runtime.h>
#include <cuda_bf16.h>
#include <cstdint>

// Shapes fixed: B=4, N=256, XDIM=256, EDIM=128, H=8, DF=32
#define SCALE 0.17677669529663687f
#define NEWX_ELEMS (4*256*256)

// ---------------- device globals (no allocation allowed) ---------------------
__device__ __align__(16) float g_Qs[4*256*256];    // (x@Wq+bq)*scale, [row][c]
__device__ __align__(16) float g_Kt[4*256*256];    // K transposed [b][c][j]
__device__ __align__(16) float g_M2[128*128];      // Wea@Weo
__device__ __align__(16) float g_bem1[256];        // bem+1
__device__ __align__(16) float g_beo2[128];        // beo + bea@Weo
// Weight slab images, bf16-split, [slab][n rows][80B padded row of 32 k]
// W1 = Wem (K=128 -> 4 slabs, N=256). W2 = [Weo; M2] (K=384 -> 12 slabs, N=128).
__device__ __align__(16) __nv_bfloat16 g_W1hi[4*256*40], g_W1lo[4*256*40];
__device__ __align__(16) __nv_bfloat16 g_W2hi[12*128*40], g_W2lo[12*128*40];

// ---------------- helpers ----------------------------------------------------
__device__ __forceinline__ uint32_t smem_u32(const void* p) {
    uint32_t a;
    asm("{ .reg .u64 t; cvta.to.shared.u64 t, %1; cvt.u32.u64 %0, t; }" : "=r"(a) : "l"(p));
    return a;
}
__device__ __forceinline__ void split_bf16(float v, __nv_bfloat16& h, __nv_bfloat16& l) {
    h = __float2bfloat16(v);
    l = __float2bfloat16(v - __bfloat162float(h));
}
__device__ __forceinline__ uint32_t pk_bf2(__nv_bfloat16 a, __nv_bfloat16 b) {
    __nv_bfloat162 t; t.x = a; t.y = b;
    return *(uint32_t*)&t;
}
__device__ __forceinline__ void ldm4(uint32_t* r, uint32_t addr) {
    asm volatile("ldmatrix.sync.aligned.m8n8.x4.shared.b16 {%0,%1,%2,%3}, [%4];"
                 : "=r"(r[0]), "=r"(r[1]), "=r"(r[2]), "=r"(r[3]) : "r"(addr));
}
__device__ __forceinline__ void mma_bf(float* d, const uint32_t* a, const uint32_t* b) {
    asm volatile("mma.sync.aligned.m16n8k16.row.col.f32.bf16.bf16.f32 "
                 "{%0,%1,%2,%3}, {%4,%5,%6,%7}, {%8,%9}, {%0,%1,%2,%3};"
                 : "+f"(d[0]), "+f"(d[1]), "+f"(d[2]), "+f"(d[3])
                 : "r"(a[0]), "r"(a[1]), "r"(a[2]), "r"(a[3]), "r"(b[0]), "r"(b[1]));
}

// ---------------- P0a: M2 = Wea@Weo, beo2, bem1 ------------------------------
__global__ void p0a_kernel(const float* __restrict__ Wea, const float* __restrict__ Weo,
                           const float* __restrict__ beo, const float* __restrict__ bea,
                           const float* __restrict__ bem) {
    int blk = blockIdx.x, tid = threadIdx.x;
    if (blk < 128) {
        if (tid < 128) {
            float s = 0.f;
            for (int c = 0; c < 256; c++) s += Wea[blk*256 + c] * Weo[c*128 + tid];
            g_M2[blk*128 + tid] = s;
        }
    } else {
        if (tid < 128) {
            float s = beo[tid];
            for (int c = 0; c < 256; c++) s += bea[c] * Weo[c*128 + tid];
            g_beo2[tid] = s;
        }
        if (tid < 256) g_bem1[tid] = bem[tid] + 1.0f;
    }
}

// ---------------- P0b: build weight slab images ------------------------------
__global__ void p0b_kernel(const float* __restrict__ Wem, const float* __restrict__ Weo) {
    int gid = blockIdx.x * 256 + threadIdx.x;
    const int NT = 64 * 256;
    // W1: Wem[k][n], k<128, n<256 -> slab k>>5, row n, pos k&31
    for (int i = gid; i < 128*256; i += NT) {
        int k = i >> 8, n = i & 255;
        __nv_bfloat16 h, l; split_bf16(Wem[i], h, l);
        int dst = (k >> 5)*10240 + n*40 + (k & 31);
        g_W1hi[dst] = h; g_W1lo[dst] = l;
    }
    // W2: k<256 -> Weo[k][n]; k>=256 -> M2[k-256][n]; n<128
    for (int i = gid; i < 384*128; i += NT) {
        int k = i >> 7, n = i & 127;
        float v = (k < 256) ? Weo[k*128 + n] : g_M2[(k - 256)*128 + n];
        __nv_bfloat16 h, l; split_bf16(v, h, l);
        int dst = (k >> 5)*5120 + n*40 + (k & 31);
        g_W2hi[dst] = h; g_W2lo[dst] = l;
    }
}

// ---------------- P1: node projections + newX (softmax collapses) ------------
__global__ __launch_bounds__(256) void p1_kernel(
    const float* __restrict__ x,
    const float* __restrict__ Wq, const float* __restrict__ bq,
    const float* __restrict__ Wk, const float* __restrict__ bk,
    const float* __restrict__ Wv, const float* __restrict__ bv,
    const float* __restrict__ Wxo, const float* __restrict__ bxo,
    float* __restrict__ outX) {
    __shared__ float xs[16][256];
    __shared__ float vs[16][256];
    int blk = blockIdx.x, tid = threadIdx.x;
    const float* xg = x + (size_t)blk * 16 * 256;
    for (int idx = tid; idx < 4096; idx += 256) xs[idx >> 8][idx & 255] = xg[idx];
    __syncthreads();
    int c = tid;
    float aq[16], ak[16], av[16];
#pragma unroll
    for (int r = 0; r < 16; r++) { aq[r] = 0.f; ak[r] = 0.f; av[r] = 0.f; }
    for (int k = 0; k < 256; k++) {
        float wq = Wq[k*256 + c], wk = Wk[k*256 + c], wv = Wv[k*256 + c];
#pragma unroll
        for (int r = 0; r < 16; r++) {
            float a = xs[r][k];
            aq[r] += a * wq; ak[r] += a * wk; av[r] += a * wv;
        }
    }
    float bqv = bq[c], bkv = bk[c], bvv = bv[c];
#pragma unroll
    for (int r = 0; r < 16; r++) {
        int row = blk*16 + r;
        g_Qs[row*256 + c] = (aq[r] + bqv) * SCALE;
        int b = row >> 8, j = row & 255;
        g_Kt[(b*256 + c)*256 + j] = ak[r] + bkv;
        vs[r][c] = av[r] + bvv;
    }
    __syncthreads();
#pragma unroll
    for (int r = 0; r < 16; r++) aq[r] = 0.f;
    for (int k = 0; k < 256; k++) {
        float w = Wxo[k*256 + c];
#pragma unroll
        for (int r = 0; r < 16; r++) aq[r] += vs[r][k] * w;
    }
    float bx = bxo[c];
#pragma unroll
    for (int r = 0; r < 16; r++) outX[(blk*16 + r)*256 + c] = aq[r] + bx;
}

// ---------------- K2: fused edge kernel with mma.sync bf16 -------------------
// Per CTA (64 edge rows): GEMM1 T=e@Wem (3-term bf16 split) -> epilogue
// Y=(T+bm)*q*K -> GEMM2 newE = [Y|e]@[Weo;M2] + beo2 (3-term split).
#define EHI 0            // e hi image  [64][256B rows]  16KB
#define ELO 16384        // e lo image                    16KB
#define YHI 32768        // Y hi image  [64][512B rows]  32KB
#define YLO 65536        // Y lo image                    32KB
#define WHI 98304        // weight slab hi                20KB
#define WLO 118784       // weight slab lo                20KB
#define QSO 139264
#define BMO 140288
#define BOO 141312
#define SMEM_BYTES 141824

__global__ __launch_bounds__(256, 1) void k2_kernel(const float* __restrict__ e,
                                                    float* __restrict__ out) {
    extern __shared__ char smem[];
    const uint32_t sb = smem_u32(smem);
    const int tid = threadIdx.x;
    const int lane = tid & 31, wid = tid >> 5;
    const int blk = blockIdx.x;
    const int bi = blk >> 2;            // b*256 + i
    const int b  = bi >> 8;
    const int j0 = (blk & 3) * 64;

    const int wm = wid & 1, wn = wid >> 1;
    const int m0 = wm * 32;             // 32 rows per warp
    const int n0  = wn * 64;            // GEMM1: 64 cols per warp
    const int n0b = wn * 32;            // GEMM2: 32 cols per warp
    const int g = lane >> 2, tg = lane & 3;

    // ldmatrix per-lane geometry
    const int rA = lane & 15;                 // A-row within 16-row tile
    const int kAsel = (lane >> 4) * 8;        // A k quadrant
    const uint32_t xorA = (uint32_t)((rA & 7) << 4);
    const int q8 = lane >> 3, rw = lane & 7;  // B lanes
    const int bQn = (q8 >> 1);                // n-subtile within pair
    const uint32_t bKoff = (uint32_t)((q8 & 1) << 4);

    float* qs = (float*)(smem + QSO);
    float* bm = (float*)(smem + BMO);
    float* bo = (float*)(smem + BOO);
    qs[tid] = g_Qs[bi*256 + tid];
    bm[tid] = g_bem1[tid];
    if (tid < 128) bo[tid] = g_beo2[tid];

    // ---- build e bf16-split images ------------------------------------------
    {
        const float4* eg = (const float4*)(e + ((size_t)(bi*256 + j0)) * 128);
        for (int i4 = tid; i4 < 2048; i4 += 256) {
            int r = i4 >> 5, k4 = (i4 & 31) * 4;
            float4 v = eg[i4];
            __nv_bfloat16 h0,h1,h2,h3,l0,l1,l2,l3;
            split_bf16(v.x,h0,l0); split_bf16(v.y,h1,l1);
            split_bf16(v.z,h2,l2); split_bf16(v.w,h3,l3);
            uint32_t addr = (uint32_t)(r*256) + (((uint32_t)(k4*2)) ^ ((uint32_t)((r&7)<<4)));
            uint2 hp; hp.x = pk_bf2(h0,h1); hp.y = pk_bf2(h2,h3);
            uint2 lp; lp.x = pk_bf2(l0,l1); lp.y = pk_bf2(l2,l3);
            *(uint2*)(smem + EHI + addr) = hp;
            *(uint2*)(smem + ELO + addr) = lp;
        }
    }
    __syncthreads();

    // ---- GEMM1: acc1[2][8][4] = e @ Wem (3-term split) ----------------------
    float acc1[2][8][4];
#pragma unroll
    for (int mt = 0; mt < 2; mt++)
#pragma unroll
        for (int nt = 0; nt < 8; nt++)
#pragma unroll
            for (int v = 0; v < 4; v++) acc1[mt][nt][v] = 0.f;

    for (int s = 0; s < 4; s++) {
        const uint4* s0 = (const uint4*)(g_W1hi + s*10240);
        const uint4* s1 = (const uint4*)(g_W1lo + s*10240);
        uint4* d0 = (uint4*)(smem + WHI);
        uint4* d1 = (uint4*)(smem + WLO);
        for (int i = tid; i < 1280; i += 256) { d0[i] = s0[i]; d1[i] = s1[i]; }
        __syncthreads();
#pragma unroll
        for (int ks = 0; ks < 32; ks += 16) {
            int kg = s*32 + ks;
            uint32_t ah[2][4], al[2][4];
#pragma unroll
            for (int mt = 0; mt < 2; mt++) {
                int row = m0 + mt*16 + rA;
                uint32_t ad = sb + EHI + (uint32_t)(row*256)
                            + (((uint32_t)(2*(kg + kAsel))) ^ xorA);
                ldm4(ah[mt], ad);
                ldm4(al[mt], ad + (ELO - EHI));
            }
            uint32_t bh[8][2], bl[8][2];
#pragma unroll
            for (int p = 0; p < 4; p++) {
                int nrow = n0 + (2*p + bQn)*8 + rw;
                uint32_t ba = sb + WHI + (uint32_t)(nrow*80) + (uint32_t)(2*ks) + bKoff;
                uint32_t t[4];
                ldm4(t, ba);
                bh[2*p][0]=t[0]; bh[2*p][1]=t[1]; bh[2*p+1][0]=t[2]; bh[2*p+1][1]=t[3];
                ldm4(t, ba + (WLO - WHI));
                bl[2*p][0]=t[0]; bl[2*p][1]=t[1]; bl[2*p+1][0]=t[2]; bl[2*p+1][1]=t[3];
            }
#pragma unroll
            for (int mt = 0; mt < 2; mt++)
#pragma unroll
                for (int nt = 0; nt < 8; nt++) {
                    mma_bf(acc1[mt][nt], ah[mt], bh[nt]);
                    mma_bf(acc1[mt][nt], al[mt], bh[nt]);
                    mma_bf(acc1[mt][nt], ah[mt], bl[nt]);
                }
        }
        __syncthreads();
    }

    // ---- epilogue: Y = (T + bm)*qs*K -> bf16-split Y images -----------------
#pragma unroll
    for (int mt = 0; mt < 2; mt++) {
        int r1 = m0 + mt*16 + g;
#pragma unroll
        for (int nt = 0; nt < 8; nt++) {
            int c = n0 + nt*8 + 2*tg;
            const float* kp = g_Kt + ((size_t)(b*256 + c))*256 + j0;
            float k00 = kp[r1],       k01 = kp[256 + r1];
            float k10 = kp[r1 + 8],   k11 = kp[256 + r1 + 8];
            float q0 = qs[c], q1 = qs[c+1], b0v = bm[c], b1v = bm[c+1];
            float y00 = (acc1[mt][nt][0] + b0v) * q0 * k00;
            float y01 = (acc1[mt][nt][1] + b1v) * q1 * k01;
            float y10 = (acc1[mt][nt][2] + b0v) * q0 * k10;
            float y11 = (acc1[mt][nt][3] + b1v) * q1 * k11;
            __nv_bfloat16 h00,h01,h10,h11,l00,l01,l10,l11;
            split_bf16(y00,h00,l00); split_bf16(y01,h01,l01);
            split_bf16(y10,h10,l10); split_bf16(y11,h11,l11);
            uint32_t xr = (uint32_t)(g << 4);
            uint32_t a0 = (uint32_t)(r1*512)     + (((uint32_t)(2*c)) ^ xr);
            uint32_t a1 = (uint32_t)((r1+8)*512) + (((uint32_t)(2*c)) ^ xr);
            *(uint32_t*)(smem + YHI + a0) = pk_bf2(h00,h01);
            *(uint32_t*)(smem + YLO + a0) = pk_bf2(l00,l01);
            *(uint32_t*)(smem + YHI + a1) = pk_bf2(h10,h11);
            *(uint32_t*)(smem + YLO + a1) = pk_bf2(l10,l11);
        }
    }
    __syncthreads();

    // ---- GEMM2: acc2 = [Y | e] @ [Weo; M2] (3-term split) -------------------
    float acc2[2][4][4];
#pragma unroll
    for (int mt = 0; mt < 2; mt++)
#pragma unroll
        for (int nt = 0; nt < 4; nt++)
#pragma unroll
            for (int v = 0; v < 4; v++) acc2[mt][nt][v] = 0.f;

    for (int s = 0; s < 12; s++) {
        const uint4* s0 = (const uint4*)(g_W2hi + s*5120);
        const uint4* s1 = (const uint4*)(g_W2lo + s*5120);
        uint4* d0 = (uint4*)(smem + WHI);
        uint4* d1 = (uint4*)(smem + WLO);
        for (int i = tid; i < 640; i += 256) { d0[i] = s0[i]; d1[i] = s1[i]; }
        __syncthreads();
        const int isY = (s < 8);
        const uint32_t abase = isY ? (uint32_t)YHI : (uint32_t)EHI;
        const uint32_t dLO   = isY ? 32768u : 16384u;
        const int strideA    = isY ? 512 : 256;
        const int kbase      = isY ? s*32 : (s - 8)*32;
#pragma unroll
        for (int ks = 0; ks < 32; ks += 16) {
            uint32_t ah[2][4], al[2][4];
#pragma unroll
            for (int mt = 0; mt < 2; mt++) {
                int row = m0 + mt*16 + rA;
                uint32_t ad = sb + abase + (uint32_t)(row*strideA)
                            + (((uint32_t)(2*(kbase + ks + kAsel))) ^ xorA);
                ldm4(ah[mt], ad);
                ldm4(al[mt], ad + dLO);
            }
            uint32_t bh[4][2], bl[4][2];
#pragma unroll
            for (int p = 0; p < 2; p++) {
                int nrow = n0b + (2*p + bQn)*8 + rw;
                uint32_t ba = sb + WHI + (uint32_t)(nrow*80) + (uint32_t)(2*ks) + bKoff;
                uint32_t t[4];
                ldm4(t, ba);
                bh[2*p][0]=t[0]; bh[2*p][1]=t[1]; bh[2*p+1][0]=t[2]; bh[2*p+1][1]=t[3];
                ldm4(t, ba + (WLO - WHI));
                bl[2*p][0]=t[0]; bl[2*p][1]=t[1]; bl[2*p+1][0]=t[2]; bl[2*p+1][1]=t[3];
            }
#pragma unroll
            for (int mt = 0; mt < 2; mt++)
#pragma unroll
                for (int nt = 0; nt < 4; nt++) {
                    mma_bf(acc2[mt][nt], ah[mt], bh[nt]);
                    mma_bf(acc2[mt][nt], al[mt], bh[nt]);
                    mma_bf(acc2[mt][nt], ah[mt], bl[nt]);
                }
        }
        __syncthreads();
    }

    // ---- store newE ----------------------------------------------------------
    float* outE = out + NEWX_ELEMS;
#pragma unroll
    for (int mt = 0; mt < 2; mt++) {
        int r1 = m0 + mt*16 + g;
#pragma unroll
        for (int nt = 0; nt < 4; nt++) {
            int c = n0b + nt*8 + 2*tg;
            float bo0 = bo[c], bo1 = bo[c+1];
            size_t row0 = (size_t)(bi*256 + j0 + r1);
            float2 v0 = make_float2(acc2[mt][nt][0] + bo0, acc2[mt][nt][1] + bo1);
            float2 v1 = make_float2(acc2[mt][nt][2] + bo0, acc2[mt][nt][3] + bo1);
            *(float2*)(outE + row0*128 + c)       = v0;
            *(float2*)(outE + (row0 + 8)*128 + c) = v1;
        }
    }
}

// ---------------- launch ------------------------------------------------------
extern "C" void kernel_launch(void* const* d_in, const int* in_sizes, int n_in,
                              void* d_out, int out_size) {
    const float* x   = (const float*)d_in[0];
    const float* e   = (const float*)d_in[1];
    const float* Wq  = (const float*)d_in[2];
    const float* bq  = (const float*)d_in[3];
    const float* Wk  = (const float*)d_in[4];
    const float* bk  = (const float*)d_in[5];
    const float* Wv  = (const float*)d_in[6];
    const float* bv  = (const float*)d_in[7];
    const float* Wem = (const float*)d_in[8];
    const float* bem = (const float*)d_in[9];
    const float* Wea = (const float*)d_in[10];
    const float* bea = (const float*)d_in[11];
    const float* Wxo = (const float*)d_in[12];
    const float* bxo = (const float*)d_in[13];
    const float* Weo = (const float*)d_in[14];
    const float* beo = (const float*)d_in[15];
    float* out = (float*)d_out;

    cudaFuncSetAttribute(k2_kernel, cudaFuncAttributeMaxDynamicSharedMemorySize, SMEM_BYTES);

    p0a_kernel<<<129, 256>>>(Wea, Weo, beo, bea, bem);
    p0b_kernel<<<64, 256>>>(Wem, Weo);
    p1_kernel<<<64, 256>>>(x, Wq, bq, Wk, bk, Wv, bv, Wxo, bxo, out);
    k2_kernel<<<4096, 256, SMEM_BYTES>>>(e, out);
}

// round 13
// speedup vs baseline: 1.2966x; 1.0032x over previous
#include <cuda_runtime.h>
#include <cuda_bf16.h>
#include <cstdint>

// Shapes fixed: B=4, N=256, XDIM=256, EDIM=128, H=8, DF=32
#define SCALE 0.17677669529663687f
#define NEWX_ELEMS (4*256*256)

// ---------------- device globals (no allocation allowed) ---------------------
__device__ __align__(16) float g_Qs[4*256*256];    // (x@Wq+bq)*scale, [row][c]
__device__ __align__(16) float g_Kt[4*256*256];    // K transposed [b][c][j]
__device__ __align__(16) float g_M2[128*128];      // Wea@Weo
__device__ __align__(16) float g_bem1[256];        // bem+1
__device__ __align__(16) float g_beo2[128];        // beo + bea@Weo
// Weight slab images, bf16-split, [slab][n rows][80B padded row of 32 k]
// W1 = Wem (K=128 -> 4 slabs, N=256). W2 = [Weo; M2] (K=384 -> 12 slabs, N=128).
__device__ __align__(16) __nv_bfloat16 g_W1hi[4*256*40], g_W1lo[4*256*40];
__device__ __align__(16) __nv_bfloat16 g_W2hi[12*128*40], g_W2lo[12*128*40];

// ---------------- helpers ----------------------------------------------------
__device__ __forceinline__ uint32_t smem_u32(const void* p) {
    uint32_t a;
    asm("{ .reg .u64 t; cvta.to.shared.u64 t, %1; cvt.u32.u64 %0, t; }" : "=r"(a) : "l"(p));
    return a;
}
__device__ __forceinline__ void split_bf16(float v, __nv_bfloat16& h, __nv_bfloat16& l) {
    h = __float2bfloat16(v);
    l = __float2bfloat16(v - __bfloat162float(h));
}
__device__ __forceinline__ uint32_t pk_bf2(__nv_bfloat16 a, __nv_bfloat16 b) {
    __nv_bfloat162 t; t.x = a; t.y = b;
    return *(uint32_t*)&t;
}
__device__ __forceinline__ void ldm4(uint32_t* r, uint32_t addr) {
    asm volatile("ldmatrix.sync.aligned.m8n8.x4.shared.b16 {%0,%1,%2,%3}, [%4];"
                 : "=r"(r[0]), "=r"(r[1]), "=r"(r[2]), "=r"(r[3]) : "r"(addr));
}
__device__ __forceinline__ void mma_bf(float* d, const uint32_t* a, const uint32_t* b) {
    asm volatile("mma.sync.aligned.m16n8k16.row.col.f32.bf16.bf16.f32 "
                 "{%0,%1,%2,%3}, {%4,%5,%6,%7}, {%8,%9}, {%0,%1,%2,%3};"
                 : "+f"(d[0]), "+f"(d[1]), "+f"(d[2]), "+f"(d[3])
                 : "r"(a[0]), "r"(a[1]), "r"(a[2]), "r"(a[3]), "r"(b[0]), "r"(b[1]));
}

// ---------------- P0a: M2 = Wea@Weo, beo2, bem1 ------------------------------
__global__ void p0a_kernel(const float* __restrict__ Wea, const float* __restrict__ Weo,
                           const float* __restrict__ beo, const float* __restrict__ bea,
                           const float* __restrict__ bem) {
    int blk = blockIdx.x, tid = threadIdx.x;
    if (blk < 128) {
        if (tid < 128) {
            float s = 0.f;
            for (int c = 0; c < 256; c++) s += Wea[blk*256 + c] * Weo[c*128 + tid];
            g_M2[blk*128 + tid] = s;
        }
    } else {
        if (tid < 128) {
            float s = beo[tid];
            for (int c = 0; c < 256; c++) s += bea[c] * Weo[c*128 + tid];
            g_beo2[tid] = s;
        }
        if (tid < 256) g_bem1[tid] = bem[tid] + 1.0f;
    }
}

// ---------------- P0b: build weight slab images ------------------------------
__global__ void p0b_kernel(const float* __restrict__ Wem, const float* __restrict__ Weo) {
    int gid = blockIdx.x * 256 + threadIdx.x;
    const int NT = 64 * 256;
    // W1: Wem[k][n], k<128, n<256 -> slab k>>5, row n, pos k&31
    for (int i = gid; i < 128*256; i += NT) {
        int k = i >> 8, n = i & 255;
        __nv_bfloat16 h, l; split_bf16(Wem[i], h, l);
        int dst = (k >> 5)*10240 + n*40 + (k & 31);
        g_W1hi[dst] = h; g_W1lo[dst] = l;
    }
    // W2: k<256 -> Weo[k][n]; k>=256 -> M2[k-256][n]; n<128
    for (int i = gid; i < 384*128; i += NT) {
        int k = i >> 7, n = i & 127;
        float v = (k < 256) ? Weo[k*128 + n] : g_M2[(k - 256)*128 + n];
        __nv_bfloat16 h, l; split_bf16(v, h, l);
        int dst = (k >> 5)*5120 + n*40 + (k & 31);
        g_W2hi[dst] = h; g_W2lo[dst] = l;
    }
}

// ---------------- P1: node projections + newX (softmax collapses) ------------
__global__ __launch_bounds__(256) void p1_kernel(
    const float* __restrict__ x,
    const float* __restrict__ Wq, const float* __restrict__ bq,
    const float* __restrict__ Wk, const float* __restrict__ bk,
    const float* __restrict__ Wv, const float* __restrict__ bv,
    const float* __restrict__ Wxo, const float* __restrict__ bxo,
    float* __restrict__ outX) {
    __shared__ float xs[16][256];
    __shared__ float vs[16][256];
    int blk = blockIdx.x, tid = threadIdx.x;
    const float* xg = x + (size_t)blk * 16 * 256;
    for (int idx = tid; idx < 4096; idx += 256) xs[idx >> 8][idx & 255] = xg[idx];
    __syncthreads();
    int c = tid;
    float aq[16], ak[16], av[16];
#pragma unroll
    for (int r = 0; r < 16; r++) { aq[r] = 0.f; ak[r] = 0.f; av[r] = 0.f; }
    for (int k = 0; k < 256; k++) {
        float wq = Wq[k*256 + c], wk = Wk[k*256 + c], wv = Wv[k*256 + c];
#pragma unroll
        for (int r = 0; r < 16; r++) {
            float a = xs[r][k];
            aq[r] += a * wq; ak[r] += a * wk; av[r] += a * wv;
        }
    }
    float bqv = bq[c], bkv = bk[c], bvv = bv[c];
#pragma unroll
    for (int r = 0; r < 16; r++) {
        int row = blk*16 + r;
        g_Qs[row*256 + c] = (aq[r] + bqv) * SCALE;
        int b = row >> 8, j = row & 255;
        g_Kt[(b*256 + c)*256 + j] = ak[r] + bkv;
        vs[r][c] = av[r] + bvv;
    }
    __syncthreads();
#pragma unroll
    for (int r = 0; r < 16; r++) aq[r] = 0.f;
    for (int k = 0; k < 256; k++) {
        float w = Wxo[k*256 + c];
#pragma unroll
        for (int r = 0; r < 16; r++) aq[r] += vs[r][k] * w;
    }
    float bx = bxo[c];
#pragma unroll
    for (int r = 0; r < 16; r++) outX[(blk*16 + r)*256 + c] = aq[r] + bx;
}

// ---------------- K2: fused edge kernel with mma.sync bf16 -------------------
// Per CTA (64 edge rows): GEMM1 T=e@Wem (3-term bf16 split) -> epilogue
// Y=(T+bm)*q*K -> GEMM2 newE = [Y|e]@[Weo;M2] + beo2 (3-term split).
#define EHI 0            // e hi image  [64][256B rows]  16KB
#define ELO 16384        // e lo image                    16KB
#define YHI 32768        // Y hi image  [64][512B rows]  32KB
#define YLO 65536        // Y lo image                    32KB
#define WHI 98304        // weight slab hi                20KB
#define WLO 118784       // weight slab lo                20KB
#define QSO 139264
#define BMO 140288
#define BOO 141312
#define SMEM_BYTES 141824

__global__ __launch_bounds__(256, 1) void k2_kernel(const float* __restrict__ e,
                                                    float* __restrict__ out) {
    extern __shared__ char smem[];
    const uint32_t sb = smem_u32(smem);
    const int tid = threadIdx.x;
    const int lane = tid & 31, wid = tid >> 5;
    const int blk = blockIdx.x;
    const int bi = blk >> 2;            // b*256 + i
    const int b  = bi >> 8;
    const int j0 = (blk & 3) * 64;

    const int wm = wid & 1, wn = wid >> 1;
    const int m0 = wm * 32;             // 32 rows per warp
    const int n0  = wn * 64;            // GEMM1: 64 cols per warp
    const int n0b = wn * 32;            // GEMM2: 32 cols per warp
    const int g = lane >> 2, tg = lane & 3;

    // ldmatrix per-lane geometry
    const int rA = lane & 15;                 // A-row within 16-row tile
    const int kAsel = (lane >> 4) * 8;        // A k quadrant
    const uint32_t xorA = (uint32_t)((rA & 7) << 4);
    const int q8 = lane >> 3, rw = lane & 7;  // B lanes
    const int bQn = (q8 >> 1);                // n-subtile within pair
    const uint32_t bKoff = (uint32_t)((q8 & 1) << 4);

    float* qs = (float*)(smem + QSO);
    float* bm = (float*)(smem + BMO);
    float* bo = (float*)(smem + BOO);
    qs[tid] = g_Qs[bi*256 + tid];
    bm[tid] = g_bem1[tid];
    if (tid < 128) bo[tid] = g_beo2[tid];

    // ---- build e bf16-split images ------------------------------------------
    {
        const float4* eg = (const float4*)(e + ((size_t)(bi*256 + j0)) * 128);
        for (int i4 = tid; i4 < 2048; i4 += 256) {
            int r = i4 >> 5, k4 = (i4 & 31) * 4;
            float4 v = eg[i4];
            __nv_bfloat16 h0,h1,h2,h3,l0,l1,l2,l3;
            split_bf16(v.x,h0,l0); split_bf16(v.y,h1,l1);
            split_bf16(v.z,h2,l2); split_bf16(v.w,h3,l3);
            uint32_t addr = (uint32_t)(r*256) + (((uint32_t)(k4*2)) ^ ((uint32_t)((r&7)<<4)));
            uint2 hp; hp.x = pk_bf2(h0,h1); hp.y = pk_bf2(h2,h3);
            uint2 lp; lp.x = pk_bf2(l0,l1); lp.y = pk_bf2(l2,l3);
            *(uint2*)(smem + EHI + addr) = hp;
            *(uint2*)(smem + ELO + addr) = lp;
        }
    }
    __syncthreads();

    // ---- GEMM1: acc1[2][8][4] = e @ Wem (3-term split) ----------------------
    float acc1[2][8][4];
#pragma unroll
    for (int mt = 0; mt < 2; mt++)
#pragma unroll
        for (int nt = 0; nt < 8; nt++)
#pragma unroll
            for (int v = 0; v < 4; v++) acc1[mt][nt][v] = 0.f;

    for (int s = 0; s < 4; s++) {
        const uint4* s0 = (const uint4*)(g_W1hi + s*10240);
        const uint4* s1 = (const uint4*)(g_W1lo + s*10240);
        uint4* d0 = (uint4*)(smem + WHI);
        uint4* d1 = (uint4*)(smem + WLO);
        for (int i = tid; i < 1280; i += 256) { d0[i] = s0[i]; d1[i] = s1[i]; }
        __syncthreads();
#pragma unroll
        for (int ks = 0; ks < 32; ks += 16) {
            int kg = s*32 + ks;
            uint32_t ah[2][4], al[2][4];
#pragma unroll
            for (int mt = 0; mt < 2; mt++) {
                int row = m0 + mt*16 + rA;
                uint32_t ad = sb + EHI + (uint32_t)(row*256)
                            + (((uint32_t)(2*(kg + kAsel))) ^ xorA);
                ldm4(ah[mt], ad);
                ldm4(al[mt], ad + (ELO - EHI));
            }
            uint32_t bh[8][2], bl[8][2];
#pragma unroll
            for (int p = 0; p < 4; p++) {
                int nrow = n0 + (2*p + bQn)*8 + rw;
                uint32_t ba = sb + WHI + (uint32_t)(nrow*80) + (uint32_t)(2*ks) + bKoff;
                uint32_t t[4];
                ldm4(t, ba);
                bh[2*p][0]=t[0]; bh[2*p][1]=t[1]; bh[2*p+1][0]=t[2]; bh[2*p+1][1]=t[3];
                ldm4(t, ba + (WLO - WHI));
                bl[2*p][0]=t[0]; bl[2*p][1]=t[1]; bl[2*p+1][0]=t[2]; bl[2*p+1][1]=t[3];
            }
#pragma unroll
            for (int mt = 0; mt < 2; mt++)
#pragma unroll
                for (int nt = 0; nt < 8; nt++) {
                    mma_bf(acc1[mt][nt], ah[mt], bh[nt]);
                    mma_bf(acc1[mt][nt], al[mt], bh[nt]);
                    mma_bf(acc1[mt][nt], ah[mt], bl[nt]);
                }
        }
        __syncthreads();
    }

    // ---- epilogue: Y = (T + bm)*qs*K -> bf16-split Y images -----------------
#pragma unroll
    for (int mt = 0; mt < 2; mt++) {
        int r1 = m0 + mt*16 + g;
#pragma unroll
        for (int nt = 0; nt < 8; nt++) {
            int c = n0 + nt*8 + 2*tg;
            const float* kp = g_Kt + ((size_t)(b*256 + c))*256 + j0;
            float k00 = kp[r1],       k01 = kp[256 + r1];
            float k10 = kp[r1 + 8],   k11 = kp[256 + r1 + 8];
            float q0 = qs[c], q1 = qs[c+1], b0v = bm[c], b1v = bm[c+1];
            float y00 = (acc1[mt][nt][0] + b0v) * q0 * k00;
            float y01 = (acc1[mt][nt][1] + b1v) * q1 * k01;
            float y10 = (acc1[mt][nt][2] + b0v) * q0 * k10;
            float y11 = (acc1[mt][nt][3] + b1v) * q1 * k11;
            __nv_bfloat16 h00,h01,h10,h11,l00,l01,l10,l11;
            split_bf16(y00,h00,l00); split_bf16(y01,h01,l01);
            split_bf16(y10,h10,l10); split_bf16(y11,h11,l11);
            uint32_t xr = (uint32_t)(g << 4);
            uint32_t a0 = (uint32_t)(r1*512)     + (((uint32_t)(2*c)) ^ xr);
            uint32_t a1 = (uint32_t)((r1+8)*512) + (((uint32_t)(2*c)) ^ xr);
            *(uint32_t*)(smem + YHI + a0) = pk_bf2(h00,h01);
            *(uint32_t*)(smem + YLO + a0) = pk_bf2(l00,l01);
            *(uint32_t*)(smem + YHI + a1) = pk_bf2(h10,h11);
            *(uint32_t*)(smem + YLO + a1) = pk_bf2(l10,l11);
        }
    }
    __syncthreads();

    // ---- GEMM2: acc2 = [Y | e] @ [Weo; M2] (3-term split) -------------------
    float acc2[2][4][4];
#pragma unroll
    for (int mt = 0; mt < 2; mt++)
#pragma unroll
        for (int nt = 0; nt < 4; nt++)
#pragma unroll
            for (int v = 0; v < 4; v++) acc2[mt][nt][v] = 0.f;

    for (int s = 0; s < 12; s++) {
        const uint4* s0 = (const uint4*)(g_W2hi + s*5120);
        const uint4* s1 = (const uint4*)(g_W2lo + s*5120);
        uint4* d0 = (uint4*)(smem + WHI);
        uint4* d1 = (uint4*)(smem + WLO);
        for (int i = tid; i < 640; i += 256) { d0[i] = s0[i]; d1[i] = s1[i]; }
        __syncthreads();
        const int isY = (s < 8);
        const uint32_t abase = isY ? (uint32_t)YHI : (uint32_t)EHI;
        const uint32_t dLO   = isY ? 32768u : 16384u;
        const int strideA    = isY ? 512 : 256;
        const int kbase      = isY ? s*32 : (s - 8)*32;
#pragma unroll
        for (int ks = 0; ks < 32; ks += 16) {
            uint32_t ah[2][4], al[2][4];
#pragma unroll
            for (int mt = 0; mt < 2; mt++) {
                int row = m0 + mt*16 + rA;
                uint32_t ad = sb + abase + (uint32_t)(row*strideA)
                            + (((uint32_t)(2*(kbase + ks + kAsel))) ^ xorA);
                ldm4(ah[mt], ad);
                ldm4(al[mt], ad + dLO);
            }
            uint32_t bh[4][2], bl[4][2];
#pragma unroll
            for (int p = 0; p < 2; p++) {
                int nrow = n0b + (2*p + bQn)*8 + rw;
                uint32_t ba = sb + WHI + (uint32_t)(nrow*80) + (uint32_t)(2*ks) + bKoff;
                uint32_t t[4];
                ldm4(t, ba);
                bh[2*p][0]=t[0]; bh[2*p][1]=t[1]; bh[2*p+1][0]=t[2]; bh[2*p+1][1]=t[3];
                ldm4(t, ba + (WLO - WHI));
                bl[2*p][0]=t[0]; bl[2*p][1]=t[1]; bl[2*p+1][0]=t[2]; bl[2*p+1][1]=t[3];
            }
#pragma unroll
            for (int mt = 0; mt < 2; mt++)
#pragma unroll
                for (int nt = 0; nt < 4; nt++) {
                    mma_bf(acc2[mt][nt], ah[mt], bh[nt]);
                    mma_bf(acc2[mt][nt], al[mt], bh[nt]);
                    mma_bf(acc2[mt][nt], ah[mt], bl[nt]);
                }
        }
        __syncthreads();
    }

    // ---- store newE ----------------------------------------------------------
    float* outE = out + NEWX_ELEMS;
#pragma unroll
    for (int mt = 0; mt < 2; mt++) {
        int r1 = m0 + mt*16 + g;
#pragma unroll
        for (int nt = 0; nt < 4; nt++) {
            int c = n0b + nt*8 + 2*tg;
            float bo0 = bo[c], bo1 = bo[c+1];
            size_t row0 = (size_t)(bi*256 + j0 + r1);
            float2 v0 = make_float2(acc2[mt][nt][0] + bo0, acc2[mt][nt][1] + bo1);
            float2 v1 = make_float2(acc2[mt][nt][2] + bo0, acc2[mt][nt][3] + bo1);
            *(float2*)(outE + row0*128 + c)       = v0;
            *(float2*)(outE + (row0 + 8)*128 + c) = v1;
        }
    }
}

// ---------------- launch ------------------------------------------------------
extern "C" void kernel_launch(void* const* d_in, const int* in_sizes, int n_in,
                              void* d_out, int out_size) {
    const float* x   = (const float*)d_in[0];
    const float* e   = (const float*)d_in[1];
    const float* Wq  = (const float*)d_in[2];
    const float* bq  = (const float*)d_in[3];
    const float* Wk  = (const float*)d_in[4];
    const float* bk  = (const float*)d_in[5];
    const float* Wv  = (const float*)d_in[6];
    const float* bv  = (const float*)d_in[7];
    const float* Wem = (const float*)d_in[8];
    const float* bem = (const float*)d_in[9];
    const float* Wea = (const float*)d_in[10];
    const float* bea = (const float*)d_in[11];
    const float* Wxo = (const float*)d_in[12];
    const float* bxo = (const float*)d_in[13];
    const float* Weo = (const float*)d_in[14];
    const float* beo = (const float*)d_in[15];
    float* out = (float*)d_out;

    cudaFuncSetAttribute(k2_kernel, cudaFuncAttributeMaxDynamicSharedMemorySize, SMEM_BYTES);

    p0a_kernel<<<129, 256>>>(Wea, Weo, beo, bea, bem);
    p0b_kernel<<<64, 256>>>(Wem, Weo);
    p1_kernel<<<64, 256>>>(x, Wq, bq, Wk, bk, Wv, bv, Wxo, bxo, out);
    k2_kernel<<<4096, 256, SMEM_BYTES>>>(e, out);
}

// round 14
// speedup vs baseline: 1.8081x; 1.3946x over previous
#include <cuda_runtime.h>
#include <cuda_bf16.h>
#include <cstdint>

// Shapes fixed: B=4, N=256, XDIM=256, EDIM=128, H=8, DF=32
#define SCALE 0.17677669529663687f
#define NEWX_ELEMS (4*256*256)

// ---------------- device globals (no allocation allowed) ---------------------
__device__ __align__(16) float g_Qs[4*256*256];    // (x@Wq+bq)*scale, [row][c]
__device__ __align__(16) float g_Kt[4*256*256];    // K transposed [b][c][j]
__device__ __align__(16) float g_M2[128*128];      // Wea@Weo
__device__ __align__(16) float g_bem1[256];        // bem+1
__device__ __align__(16) float g_beo2[128];        // beo + bea@Weo
// Weight slab images, bf16-split, [slab][n rows][80B padded row of 32 k]
// W1 = Wem (K=128 -> 4 slabs, N=256). W2 = [Weo; M2] (K=384 -> 12 slabs, N=128).
__device__ __align__(16) __nv_bfloat16 g_W1hi[4*256*40], g_W1lo[4*256*40];
__device__ __align__(16) __nv_bfloat16 g_W2hi[12*128*40], g_W2lo[12*128*40];

// ---------------- helpers ----------------------------------------------------
__device__ __forceinline__ uint32_t smem_u32(const void* p) {
    uint32_t a;
    asm("{ .reg .u64 t; cvta.to.shared.u64 t, %1; cvt.u32.u64 %0, t; }" : "=r"(a) : "l"(p));
    return a;
}
__device__ __forceinline__ void split_bf16(float v, __nv_bfloat16& h, __nv_bfloat16& l) {
    h = __float2bfloat16(v);
    l = __float2bfloat16(v - __bfloat162float(h));
}
__device__ __forceinline__ uint32_t pk_bf2(__nv_bfloat16 a, __nv_bfloat16 b) {
    __nv_bfloat162 t; t.x = a; t.y = b;
    return *(uint32_t*)&t;
}
__device__ __forceinline__ void ldm4(uint32_t* r, uint32_t addr) {
    asm volatile("ldmatrix.sync.aligned.m8n8.x4.shared.b16 {%0,%1,%2,%3}, [%4];"
                 : "=r"(r[0]), "=r"(r[1]), "=r"(r[2]), "=r"(r[3]) : "r"(addr));
}
__device__ __forceinline__ void mma_bf(float* d, const uint32_t* a, const uint32_t* b) {
    asm volatile("mma.sync.aligned.m16n8k16.row.col.f32.bf16.bf16.f32 "
                 "{%0,%1,%2,%3}, {%4,%5,%6,%7}, {%8,%9}, {%0,%1,%2,%3};"
                 : "+f"(d[0]), "+f"(d[1]), "+f"(d[2]), "+f"(d[3])
                 : "r"(a[0]), "r"(a[1]), "r"(a[2]), "r"(a[3]), "r"(b[0]), "r"(b[1]));
}
__device__ __forceinline__ void cp16(uint32_t saddr, const void* g) {
    asm volatile("cp.async.cg.shared.global [%0], [%1], 16;" :: "r"(saddr), "l"(g) : "memory");
}
#define CP_COMMIT() asm volatile("cp.async.commit_group;" ::: "memory")
#define CP_WAIT0()  asm volatile("cp.async.wait_group 0;" ::: "memory")

// ---------------- P0a: M2 = Wea@Weo, beo2, bem1 ------------------------------
__global__ void p0a_kernel(const float* __restrict__ Wea, const float* __restrict__ Weo,
                           const float* __restrict__ beo, const float* __restrict__ bea,
                           const float* __restrict__ bem) {
    int blk = blockIdx.x, tid = threadIdx.x;
    if (blk < 128) {
        if (tid < 128) {
            float s = 0.f;
            for (int c = 0; c < 256; c++) s += Wea[blk*256 + c] * Weo[c*128 + tid];
            g_M2[blk*128 + tid] = s;
        }
    } else {
        if (tid < 128) {
            float s = beo[tid];
            for (int c = 0; c < 256; c++) s += bea[c] * Weo[c*128 + tid];
            g_beo2[tid] = s;
        }
        if (tid < 256) g_bem1[tid] = bem[tid] + 1.0f;
    }
}

// ---------------- P0b: build weight slab images ------------------------------
__global__ void p0b_kernel(const float* __restrict__ Wem, const float* __restrict__ Weo) {
    int gid = blockIdx.x * 256 + threadIdx.x;
    const int NT = 64 * 256;
    for (int i = gid; i < 128*256; i += NT) {
        int k = i >> 8, n = i & 255;
        __nv_bfloat16 h, l; split_bf16(Wem[i], h, l);
        int dst = (k >> 5)*10240 + n*40 + (k & 31);
        g_W1hi[dst] = h; g_W1lo[dst] = l;
    }
    for (int i = gid; i < 384*128; i += NT) {
        int k = i >> 7, n = i & 127;
        float v = (k < 256) ? Weo[k*128 + n] : g_M2[(k - 256)*128 + n];
        __nv_bfloat16 h, l; split_bf16(v, h, l);
        int dst = (k >> 5)*5120 + n*40 + (k & 31);
        g_W2hi[dst] = h; g_W2lo[dst] = l;
    }
}

// ---------------- P1: node projections + newX (softmax collapses) ------------
__global__ __launch_bounds__(256) void p1_kernel(
    const float* __restrict__ x,
    const float* __restrict__ Wq, const float* __restrict__ bq,
    const float* __restrict__ Wk, const float* __restrict__ bk,
    const float* __restrict__ Wv, const float* __restrict__ bv,
    const float* __restrict__ Wxo, const float* __restrict__ bxo,
    float* __restrict__ outX) {
    __shared__ float xs[16][256];
    __shared__ float vs[16][256];
    int blk = blockIdx.x, tid = threadIdx.x;
    const float* xg = x + (size_t)blk * 16 * 256;
    for (int idx = tid; idx < 4096; idx += 256) xs[idx >> 8][idx & 255] = xg[idx];
    __syncthreads();
    int c = tid;
    float aq[16], ak[16], av[16];
#pragma unroll
    for (int r = 0; r < 16; r++) { aq[r] = 0.f; ak[r] = 0.f; av[r] = 0.f; }
    for (int k = 0; k < 256; k++) {
        float wq = Wq[k*256 + c], wk = Wk[k*256 + c], wv = Wv[k*256 + c];
#pragma unroll
        for (int r = 0; r < 16; r++) {
            float a = xs[r][k];
            aq[r] += a * wq; ak[r] += a * wk; av[r] += a * wv;
        }
    }
    float bqv = bq[c], bkv = bk[c], bvv = bv[c];
#pragma unroll
    for (int r = 0; r < 16; r++) {
        int row = blk*16 + r;
        g_Qs[row*256 + c] = (aq[r] + bqv) * SCALE;
        int b = row >> 8, j = row & 255;
        g_Kt[(b*256 + c)*256 + j] = ak[r] + bkv;
        vs[r][c] = av[r] + bvv;
    }
    __syncthreads();
#pragma unroll
    for (int r = 0; r < 16; r++) aq[r] = 0.f;
    for (int k = 0; k < 256; k++) {
        float w = Wxo[k*256 + c];
#pragma unroll
        for (int r = 0; r < 16; r++) aq[r] += vs[r][k] * w;
    }
    float bx = bxo[c];
#pragma unroll
    for (int r = 0; r < 16; r++) outX[(blk*16 + r)*256 + c] = aq[r] + bx;
}

// ---------------- K2: fused edge kernel, cp.async double-buffered ------------
#define EHI 0            // e hi image  [64][256B rows]  16KB
#define ELO 16384        // e lo image                   16KB
#define YHI 32768        // Y hi image  [64][512B rows]  32KB
#define YLO 65536        // Y lo image                   32KB
#define WBUF 98304       // weight staging, 2x40KB       80KB
#define QSO 180224
#define BMO 181248
#define BOO 182272
#define SMEM_BYTES 182784

__global__ __launch_bounds__(256, 1) void k2_kernel(const float* __restrict__ e,
                                                    float* __restrict__ out) {
    extern __shared__ char smem[];
    const uint32_t sb = smem_u32(smem);
    const int tid = threadIdx.x;
    const int lane = tid & 31, wid = tid >> 5;
    const int blk = blockIdx.x;
    const int bi = blk >> 2;            // b*256 + i
    const int b  = bi >> 8;
    const int j0 = (blk & 3) * 64;

    const int wm = wid & 1, wn = wid >> 1;
    const int m0 = wm * 32;
    const int n0  = wn * 64;
    const int n0b = wn * 32;
    const int g = lane >> 2, tg = lane & 3;

    const int rA = lane & 15;
    const int kAsel = (lane >> 4) * 8;
    const uint32_t xorA = (uint32_t)((rA & 7) << 4);
    const int q8 = lane >> 3, rw = lane & 7;
    const int bQn = (q8 >> 1);
    const uint32_t bKoff = (uint32_t)((q8 & 1) << 4);

    float* qs = (float*)(smem + QSO);
    float* bm = (float*)(smem + BMO);
    float* bo = (float*)(smem + BOO);
    qs[tid] = g_Qs[bi*256 + tid];
    bm[tid] = g_bem1[tid];
    if (tid < 128) bo[tid] = g_beo2[tid];

    // ---- prefetch W1 slab 0 (cp.async) --------------------------------------
    {
        const char* srcH = (const char*)(g_W1hi);
        const char* srcL = (const char*)(g_W1lo);
        uint32_t dH = sb + WBUF, dL = dH + 20480;
        for (int i = tid*16; i < 20480; i += 256*16) {
            cp16(dH + i, srcH + i);
            cp16(dL + i, srcL + i);
        }
        CP_COMMIT();
    }

    // ---- build e bf16-split images ------------------------------------------
    {
        const float4* eg = (const float4*)(e + ((size_t)(bi*256 + j0)) * 128);
        for (int i4 = tid; i4 < 2048; i4 += 256) {
            int r = i4 >> 5, k4 = (i4 & 31) * 4;
            float4 v = eg[i4];
            __nv_bfloat16 h0,h1,h2,h3,l0,l1,l2,l3;
            split_bf16(v.x,h0,l0); split_bf16(v.y,h1,l1);
            split_bf16(v.z,h2,l2); split_bf16(v.w,h3,l3);
            uint32_t addr = (uint32_t)(r*256) + (((uint32_t)(k4*2)) ^ ((uint32_t)((r&7)<<4)));
            uint2 hp; hp.x = pk_bf2(h0,h1); hp.y = pk_bf2(h2,h3);
            uint2 lp; lp.x = pk_bf2(l0,l1); lp.y = pk_bf2(l2,l3);
            *(uint2*)(smem + EHI + addr) = hp;
            *(uint2*)(smem + ELO + addr) = lp;
        }
    }

    // ---- GEMM1: acc1[2][8][4] = e @ Wem (3-term split), pipelined ----------
    float acc1[2][8][4];
#pragma unroll
    for (int mt = 0; mt < 2; mt++)
#pragma unroll
        for (int nt = 0; nt < 8; nt++)
#pragma unroll
            for (int v = 0; v < 4; v++) acc1[mt][nt][v] = 0.f;

    for (int s = 0; s < 4; s++) {
        CP_WAIT0();
        __syncthreads();
        if (s + 1 < 4) {
            const char* srcH = (const char*)(g_W1hi + (s+1)*10240);
            const char* srcL = (const char*)(g_W1lo + (s+1)*10240);
            uint32_t dH = sb + WBUF + ((s+1)&1)*40960, dL = dH + 20480;
            for (int i = tid*16; i < 20480; i += 256*16) {
                cp16(dH + i, srcH + i);
                cp16(dL + i, srcL + i);
            }
            CP_COMMIT();
        }
        const uint32_t wbase = sb + WBUF + (s & 1)*40960;
#pragma unroll
        for (int ks = 0; ks < 32; ks += 16) {
            int kg = s*32 + ks;
            uint32_t ah[2][4], al[2][4];
#pragma unroll
            for (int mt = 0; mt < 2; mt++) {
                int row = m0 + mt*16 + rA;
                uint32_t ad = sb + EHI + (uint32_t)(row*256)
                            + (((uint32_t)(2*(kg + kAsel))) ^ xorA);
                ldm4(ah[mt], ad);
                ldm4(al[mt], ad + (ELO - EHI));
            }
            uint32_t bh[8][2], bl[8][2];
#pragma unroll
            for (int p = 0; p < 4; p++) {
                int nrow = n0 + (2*p + bQn)*8 + rw;
                uint32_t ba = wbase + (uint32_t)(nrow*80) + (uint32_t)(2*ks) + bKoff;
                uint32_t t[4];
                ldm4(t, ba);
                bh[2*p][0]=t[0]; bh[2*p][1]=t[1]; bh[2*p+1][0]=t[2]; bh[2*p+1][1]=t[3];
                ldm4(t, ba + 20480);
                bl[2*p][0]=t[0]; bl[2*p][1]=t[1]; bl[2*p+1][0]=t[2]; bl[2*p+1][1]=t[3];
            }
#pragma unroll
            for (int mt = 0; mt < 2; mt++)
#pragma unroll
                for (int nt = 0; nt < 8; nt++) {
                    mma_bf(acc1[mt][nt], ah[mt], bh[nt]);
                    mma_bf(acc1[mt][nt], al[mt], bh[nt]);
                    mma_bf(acc1[mt][nt], ah[mt], bl[nt]);
                }
        }
    }

    // ---- prefetch W2 slab 0 during epilogue ---------------------------------
    {
        const char* srcH = (const char*)(g_W2hi);
        const char* srcL = (const char*)(g_W2lo);
        uint32_t dH = sb + WBUF, dL = dH + 10240;
        for (int i = tid*16; i < 10240; i += 256*16) {
            cp16(dH + i, srcH + i);
            cp16(dL + i, srcL + i);
        }
        CP_COMMIT();
    }

    // ---- epilogue: Y = (T + bm)*qs*K -> bf16-split Y images -----------------
#pragma unroll
    for (int mt = 0; mt < 2; mt++) {
        int r1 = m0 + mt*16 + g;
#pragma unroll
        for (int nt = 0; nt < 8; nt++) {
            int c = n0 + nt*8 + 2*tg;
            const float* kp = g_Kt + ((size_t)(b*256 + c))*256 + j0;
            float k00 = kp[r1],       k01 = kp[256 + r1];
            float k10 = kp[r1 + 8],   k11 = kp[256 + r1 + 8];
            float q0 = qs[c], q1 = qs[c+1], b0v = bm[c], b1v = bm[c+1];
            float y00 = (acc1[mt][nt][0] + b0v) * q0 * k00;
            float y01 = (acc1[mt][nt][1] + b1v) * q1 * k01;
            float y10 = (acc1[mt][nt][2] + b0v) * q0 * k10;
            float y11 = (acc1[mt][nt][3] + b1v) * q1 * k11;
            __nv_bfloat16 h00,h01,h10,h11,l00,l01,l10,l11;
            split_bf16(y00,h00,l00); split_bf16(y01,h01,l01);
            split_bf16(y10,h10,l10); split_bf16(y11,h11,l11);
            uint32_t xr = (uint32_t)(g << 4);
            uint32_t a0 = (uint32_t)(r1*512)     + (((uint32_t)(2*c)) ^ xr);
            uint32_t a1 = (uint32_t)((r1+8)*512) + (((uint32_t)(2*c)) ^ xr);
            *(uint32_t*)(smem + YHI + a0) = pk_bf2(h00,h01);
            *(uint32_t*)(smem + YLO + a0) = pk_bf2(l00,l01);
            *(uint32_t*)(smem + YHI + a1) = pk_bf2(h10,h11);
            *(uint32_t*)(smem + YLO + a1) = pk_bf2(l10,l11);
        }
    }

    // ---- GEMM2: acc2 = [Y | e] @ [Weo; M2] (3-term split), pipelined --------
    float acc2[2][4][4];
#pragma unroll
    for (int mt = 0; mt < 2; mt++)
#pragma unroll
        for (int nt = 0; nt < 4; nt++)
#pragma unroll
            for (int v = 0; v < 4; v++) acc2[mt][nt][v] = 0.f;

    for (int s = 0; s < 12; s++) {
        CP_WAIT0();
        __syncthreads();
        if (s + 1 < 12) {
            const char* srcH = (const char*)(g_W2hi + (s+1)*5120);
            const char* srcL = (const char*)(g_W2lo + (s+1)*5120);
            uint32_t dH = sb + WBUF + ((s+1)&1)*20480, dL = dH + 10240;
            for (int i = tid*16; i < 10240; i += 256*16) {
                cp16(dH + i, srcH + i);
                cp16(dL + i, srcL + i);
            }
            CP_COMMIT();
        }
        const uint32_t wbase = sb + WBUF + (s & 1)*20480;
        const int isY = (s < 8);
        const uint32_t abase = isY ? (uint32_t)YHI : (uint32_t)EHI;
        const uint32_t dLO   = isY ? 32768u : 16384u;
        const int strideA    = isY ? 512 : 256;
        const int kbase      = isY ? s*32 : (s - 8)*32;
#pragma unroll
        for (int ks = 0; ks < 32; ks += 16) {
            uint32_t ah[2][4], al[2][4];
#pragma unroll
            for (int mt = 0; mt < 2; mt++) {
                int row = m0 + mt*16 + rA;
                uint32_t ad = sb + abase + (uint32_t)(row*strideA)
                            + (((uint32_t)(2*(kbase + ks + kAsel))) ^ xorA);
                ldm4(ah[mt], ad);
                ldm4(al[mt], ad + dLO);
            }
            uint32_t bh[4][2], bl[4][2];
#pragma unroll
            for (int p = 0; p < 2; p++) {
                int nrow = n0b + (2*p + bQn)*8 + rw;
                uint32_t ba = wbase + (uint32_t)(nrow*80) + (uint32_t)(2*ks) + bKoff;
                uint32_t t[4];
                ldm4(t, ba);
                bh[2*p][0]=t[0]; bh[2*p][1]=t[1]; bh[2*p+1][0]=t[2]; bh[2*p+1][1]=t[3];
                ldm4(t, ba + 10240);
                bl[2*p][0]=t[0]; bl[2*p][1]=t[1]; bl[2*p+1][0]=t[2]; bl[2*p+1][1]=t[3];
            }
#pragma unroll
            for (int mt = 0; mt < 2; mt++)
#pragma unroll
                for (int nt = 0; nt < 4; nt++) {
                    mma_bf(acc2[mt][nt], ah[mt], bh[nt]);
                    mma_bf(acc2[mt][nt], al[mt], bh[nt]);
                    mma_bf(acc2[mt][nt], ah[mt], bl[nt]);
                }
        }
    }

    // ---- store newE ----------------------------------------------------------
    float* outE = out + NEWX_ELEMS;
#pragma unroll
    for (int mt = 0; mt < 2; mt++) {
        int r1 = m0 + mt*16 + g;
#pragma unroll
        for (int nt = 0; nt < 4; nt++) {
            int c = n0b + nt*8 + 2*tg;
            float bo0 = bo[c], bo1 = bo[c+1];
            size_t row0 = (size_t)(bi*256 + j0 + r1);
            float2 v0 = make_float2(acc2[mt][nt][0] + bo0, acc2[mt][nt][1] + bo1);
            float2 v1 = make_float2(acc2[mt][nt][2] + bo0, acc2[mt][nt][3] + bo1);
            *(float2*)(outE + row0*128 + c)       = v0;
            *(float2*)(outE + (row0 + 8)*128 + c) = v1;
        }
    }
}

// ---------------- launch ------------------------------------------------------
extern "C" void kernel_launch(void* const* d_in, const int* in_sizes, int n_in,
                              void* d_out, int out_size) {
    const float* x   = (const float*)d_in[0];
    const float* e   = (const float*)d_in[1];
    const float* Wq  = (const float*)d_in[2];
    const float* bq  = (const float*)d_in[3];
    const float* Wk  = (const float*)d_in[4];
    const float* bk  = (const float*)d_in[5];
    const float* Wv  = (const float*)d_in[6];
    const float* bv  = (const float*)d_in[7];
    const float* Wem = (const float*)d_in[8];
    const float* bem = (const float*)d_in[9];
    const float* Wea = (const float*)d_in[10];
    const float* bea = (const float*)d_in[11];
    const float* Wxo = (const float*)d_in[12];
    const float* bxo = (const float*)d_in[13];
    const float* Weo = (const float*)d_in[14];
    const float* beo = (const float*)d_in[15];
    float* out = (float*)d_out;

    cudaFuncSetAttribute(k2_kernel, cudaFuncAttributeMaxDynamicSharedMemorySize, SMEM_BYTES);

    p0a_kernel<<<129, 256>>>(Wea, Weo, beo, bea, bem);
    p0b_kernel<<<64, 256>>>(Wem, Weo);
    p1_kernel<<<64, 256>>>(x, Wq, bq, Wk, bk, Wv, bv, Wxo, bxo, out);
    k2_kernel<<<4096, 256, SMEM_BYTES>>>(e, out);
}

// round 15
// speedup vs baseline: 1.8195x; 1.0063x over previous
#include <cuda_runtime.h>
#include <cuda_bf16.h>
#include <cstdint>

// Shapes fixed: B=4, N=256, XDIM=256, EDIM=128, H=8, DF=32
#define SCALE 0.17677669529663687f
#define NEWX_ELEMS (4*256*256)

// ---------------- device globals (no allocation allowed) ---------------------
__device__ __align__(16) float g_Qs[4*256*256];    // (x@Wq+bq)*scale, [row][c]
__device__ __align__(16) float g_Kt[4*256*256];    // K transposed [b][c][j]
__device__ __align__(16) float g_M2[128*128];      // Wea@Weo
__device__ __align__(16) float g_bem1[256];        // bem+1
__device__ __align__(16) float g_beo2[128];        // beo + bea@Weo
// Weight slab images, bf16-split, [slab][n rows][80B padded row of 32 k]
// W1 = Wem (K=128 -> 4 slabs, N=256). W2 = [Weo; M2] (K=384 -> 12 slabs, N=128).
__device__ __align__(16) __nv_bfloat16 g_W1hi[4*256*40], g_W1lo[4*256*40];
__device__ __align__(16) __nv_bfloat16 g_W2hi[12*128*40], g_W2lo[12*128*40];

// ---------------- helpers ----------------------------------------------------
__device__ __forceinline__ uint32_t smem_u32(const void* p) {
    uint32_t a;
    asm("{ .reg .u64 t; cvta.to.shared.u64 t, %1; cvt.u32.u64 %0, t; }" : "=r"(a) : "l"(p));
    return a;
}
__device__ __forceinline__ void split_bf16(float v, __nv_bfloat16& h, __nv_bfloat16& l) {
    h = __float2bfloat16(v);
    l = __float2bfloat16(v - __bfloat162float(h));
}
__device__ __forceinline__ uint32_t pk_bf2(__nv_bfloat16 a, __nv_bfloat16 b) {
    __nv_bfloat162 t; t.x = a; t.y = b;
    return *(uint32_t*)&t;
}
__device__ __forceinline__ void ldm4(uint32_t* r, uint32_t addr) {
    asm volatile("ldmatrix.sync.aligned.m8n8.x4.shared.b16 {%0,%1,%2,%3}, [%4];"
                 : "=r"(r[0]), "=r"(r[1]), "=r"(r[2]), "=r"(r[3]) : "r"(addr));
}
__device__ __forceinline__ void mma_bf(float* d, const uint32_t* a, const uint32_t* b) {
    asm volatile("mma.sync.aligned.m16n8k16.row.col.f32.bf16.bf16.f32 "
                 "{%0,%1,%2,%3}, {%4,%5,%6,%7}, {%8,%9}, {%0,%1,%2,%3};"
                 : "+f"(d[0]), "+f"(d[1]), "+f"(d[2]), "+f"(d[3])
                 : "r"(a[0]), "r"(a[1]), "r"(a[2]), "r"(a[3]), "r"(b[0]), "r"(b[1]));
}
__device__ __forceinline__ void cp16(uint32_t saddr, const void* g) {
    asm volatile("cp.async.cg.shared.global [%0], [%1], 16;" :: "r"(saddr), "l"(g) : "memory");
}
#define CP_COMMIT() asm volatile("cp.async.commit_group;" ::: "memory")
#define CP_WAIT0()  asm volatile("cp.async.wait_group 0;" ::: "memory")

// ---------------- P0a: M2 = Wea@Weo, beo2, bem1 ------------------------------
__global__ void p0a_kernel(const float* __restrict__ Wea, const float* __restrict__ Weo,
                           const float* __restrict__ beo, const float* __restrict__ bea,
                           const float* __restrict__ bem) {
    int blk = blockIdx.x, tid = threadIdx.x;
    if (blk < 128) {
        if (tid < 128) {
            float s = 0.f;
            for (int c = 0; c < 256; c++) s += Wea[blk*256 + c] * Weo[c*128 + tid];
            g_M2[blk*128 + tid] = s;
        }
    } else {
        if (tid < 128) {
            float s = beo[tid];
            for (int c = 0; c < 256; c++) s += bea[c] * Weo[c*128 + tid];
            g_beo2[tid] = s;
        }
        if (tid < 256) g_bem1[tid] = bem[tid] + 1.0f;
    }
}

// ---------------- P0b: build weight slab images ------------------------------
__global__ void p0b_kernel(const float* __restrict__ Wem, const float* __restrict__ Weo) {
    int gid = blockIdx.x * 256 + threadIdx.x;
    const int NT = 64 * 256;
    for (int i = gid; i < 128*256; i += NT) {
        int k = i >> 8, n = i & 255;
        __nv_bfloat16 h, l; split_bf16(Wem[i], h, l);
        int dst = (k >> 5)*10240 + n*40 + (k & 31);
        g_W1hi[dst] = h; g_W1lo[dst] = l;
    }
    for (int i = gid; i < 384*128; i += NT) {
        int k = i >> 7, n = i & 127;
        float v = (k < 256) ? Weo[k*128 + n] : g_M2[(k - 256)*128 + n];
        __nv_bfloat16 h, l; split_bf16(v, h, l);
        int dst = (k >> 5)*5120 + n*40 + (k & 31);
        g_W2hi[dst] = h; g_W2lo[dst] = l;
    }
}

// ---------------- P1: node projections + newX (softmax collapses) ------------
__global__ __launch_bounds__(256) void p1_kernel(
    const float* __restrict__ x,
    const float* __restrict__ Wq, const float* __restrict__ bq,
    const float* __restrict__ Wk, const float* __restrict__ bk,
    const float* __restrict__ Wv, const float* __restrict__ bv,
    const float* __restrict__ Wxo, const float* __restrict__ bxo,
    float* __restrict__ outX) {
    __shared__ float xs[16][256];
    __shared__ float vs[16][256];
    int blk = blockIdx.x, tid = threadIdx.x;
    const float* xg = x + (size_t)blk * 16 * 256;
    for (int idx = tid; idx < 4096; idx += 256) xs[idx >> 8][idx & 255] = xg[idx];
    __syncthreads();
    int c = tid;
    float aq[16], ak[16], av[16];
#pragma unroll
    for (int r = 0; r < 16; r++) { aq[r] = 0.f; ak[r] = 0.f; av[r] = 0.f; }
    for (int k = 0; k < 256; k++) {
        float wq = Wq[k*256 + c], wk = Wk[k*256 + c], wv = Wv[k*256 + c];
#pragma unroll
        for (int r = 0; r < 16; r++) {
            float a = xs[r][k];
            aq[r] += a * wq; ak[r] += a * wk; av[r] += a * wv;
        }
    }
    float bqv = bq[c], bkv = bk[c], bvv = bv[c];
#pragma unroll
    for (int r = 0; r < 16; r++) {
        int row = blk*16 + r;
        g_Qs[row*256 + c] = (aq[r] + bqv) * SCALE;
        int b = row >> 8, j = row & 255;
        g_Kt[(b*256 + c)*256 + j] = ak[r] + bkv;
        vs[r][c] = av[r] + bvv;
    }
    __syncthreads();
#pragma unroll
    for (int r = 0; r < 16; r++) aq[r] = 0.f;
    for (int k = 0; k < 256; k++) {
        float w = Wxo[k*256 + c];
#pragma unroll
        for (int r = 0; r < 16; r++) aq[r] += vs[r][k] * w;
    }
    float bx = bxo[c];
#pragma unroll
    for (int r = 0; r < 16; r++) outX[(blk*16 + r)*256 + c] = aq[r] + bx;
}

// ---------------- K2: fused edge kernel, cp.async double-buffered ------------
#define EHI 0            // e hi image  [64][256B rows]  16KB
#define ELO 16384        // e lo image                   16KB
#define YHI 32768        // Y hi image  [64][512B rows]  32KB
#define YLO 65536        // Y lo image                   32KB
#define WBUF 98304       // weight staging, 2x40KB       80KB
#define QSO 180224
#define BMO 181248
#define BOO 182272
#define SMEM_BYTES 182784

__global__ __launch_bounds__(256, 1) void k2_kernel(const float* __restrict__ e,
                                                    float* __restrict__ out) {
    extern __shared__ char smem[];
    const uint32_t sb = smem_u32(smem);
    const int tid = threadIdx.x;
    const int lane = tid & 31, wid = tid >> 5;
    const int blk = blockIdx.x;
    const int bi = blk >> 2;            // b*256 + i
    const int b  = bi >> 8;
    const int j0 = (blk & 3) * 64;

    const int wm = wid & 1, wn = wid >> 1;
    const int m0 = wm * 32;
    const int n0  = wn * 64;
    const int n0b = wn * 32;
    const int g = lane >> 2, tg = lane & 3;

    const int rA = lane & 15;
    const int kAsel = (lane >> 4) * 8;
    const uint32_t xorA = (uint32_t)((rA & 7) << 4);
    const int q8 = lane >> 3, rw = lane & 7;
    const int bQn = (q8 >> 1);
    const uint32_t bKoff = (uint32_t)((q8 & 1) << 4);

    float* qs = (float*)(smem + QSO);
    float* bm = (float*)(smem + BMO);
    float* bo = (float*)(smem + BOO);
    qs[tid] = g_Qs[bi*256 + tid];
    bm[tid] = g_bem1[tid];
    if (tid < 128) bo[tid] = g_beo2[tid];

    // ---- prefetch W1 slab 0 (cp.async) --------------------------------------
    {
        const char* srcH = (const char*)(g_W1hi);
        const char* srcL = (const char*)(g_W1lo);
        uint32_t dH = sb + WBUF, dL = dH + 20480;
        for (int i = tid*16; i < 20480; i += 256*16) {
            cp16(dH + i, srcH + i);
            cp16(dL + i, srcL + i);
        }
        CP_COMMIT();
    }

    // ---- build e bf16-split images ------------------------------------------
    {
        const float4* eg = (const float4*)(e + ((size_t)(bi*256 + j0)) * 128);
        for (int i4 = tid; i4 < 2048; i4 += 256) {
            int r = i4 >> 5, k4 = (i4 & 31) * 4;
            float4 v = eg[i4];
            __nv_bfloat16 h0,h1,h2,h3,l0,l1,l2,l3;
            split_bf16(v.x,h0,l0); split_bf16(v.y,h1,l1);
            split_bf16(v.z,h2,l2); split_bf16(v.w,h3,l3);
            uint32_t addr = (uint32_t)(r*256) + (((uint32_t)(k4*2)) ^ ((uint32_t)((r&7)<<4)));
            uint2 hp; hp.x = pk_bf2(h0,h1); hp.y = pk_bf2(h2,h3);
            uint2 lp; lp.x = pk_bf2(l0,l1); lp.y = pk_bf2(l2,l3);
            *(uint2*)(smem + EHI + addr) = hp;
            *(uint2*)(smem + ELO + addr) = lp;
        }
    }

    // ---- GEMM1: acc1[2][8][4] = e @ Wem (3-term split), pipelined ----------
    float acc1[2][8][4];
#pragma unroll
    for (int mt = 0; mt < 2; mt++)
#pragma unroll
        for (int nt = 0; nt < 8; nt++)
#pragma unroll
            for (int v = 0; v < 4; v++) acc1[mt][nt][v] = 0.f;

    for (int s = 0; s < 4; s++) {
        CP_WAIT0();
        __syncthreads();
        if (s + 1 < 4) {
            const char* srcH = (const char*)(g_W1hi + (s+1)*10240);
            const char* srcL = (const char*)(g_W1lo + (s+1)*10240);
            uint32_t dH = sb + WBUF + ((s+1)&1)*40960, dL = dH + 20480;
            for (int i = tid*16; i < 20480; i += 256*16) {
                cp16(dH + i, srcH + i);
                cp16(dL + i, srcL + i);
            }
            CP_COMMIT();
        }
        const uint32_t wbase = sb + WBUF + (s & 1)*40960;
#pragma unroll
        for (int ks = 0; ks < 32; ks += 16) {
            int kg = s*32 + ks;
            uint32_t ah[2][4], al[2][4];
#pragma unroll
            for (int mt = 0; mt < 2; mt++) {
                int row = m0 + mt*16 + rA;
                uint32_t ad = sb + EHI + (uint32_t)(row*256)
                            + (((uint32_t)(2*(kg + kAsel))) ^ xorA);
                ldm4(ah[mt], ad);
                ldm4(al[mt], ad + (ELO - EHI));
            }
            uint32_t bh[8][2], bl[8][2];
#pragma unroll
            for (int p = 0; p < 4; p++) {
                int nrow = n0 + (2*p + bQn)*8 + rw;
                uint32_t ba = wbase + (uint32_t)(nrow*80) + (uint32_t)(2*ks) + bKoff;
                uint32_t t[4];
                ldm4(t, ba);
                bh[2*p][0]=t[0]; bh[2*p][1]=t[1]; bh[2*p+1][0]=t[2]; bh[2*p+1][1]=t[3];
                ldm4(t, ba + 20480);
                bl[2*p][0]=t[0]; bl[2*p][1]=t[1]; bl[2*p+1][0]=t[2]; bl[2*p+1][1]=t[3];
            }
#pragma unroll
            for (int mt = 0; mt < 2; mt++)
#pragma unroll
                for (int nt = 0; nt < 8; nt++) {
                    mma_bf(acc1[mt][nt], ah[mt], bh[nt]);
                    mma_bf(acc1[mt][nt], al[mt], bh[nt]);
                    mma_bf(acc1[mt][nt], ah[mt], bl[nt]);
                }
        }
    }

    // ---- prefetch W2 slab 0 during epilogue ---------------------------------
    {
        const char* srcH = (const char*)(g_W2hi);
        const char* srcL = (const char*)(g_W2lo);
        uint32_t dH = sb + WBUF, dL = dH + 10240;
        for (int i = tid*16; i < 10240; i += 256*16) {
            cp16(dH + i, srcH + i);
            cp16(dL + i, srcL + i);
        }
        CP_COMMIT();
    }

    // ---- epilogue: Y = (T + bm)*qs*K -> bf16-split Y images -----------------
#pragma unroll
    for (int mt = 0; mt < 2; mt++) {
        int r1 = m0 + mt*16 + g;
#pragma unroll
        for (int nt = 0; nt < 8; nt++) {
            int c = n0 + nt*8 + 2*tg;
            const float* kp = g_Kt + ((size_t)(b*256 + c))*256 + j0;
            float k00 = kp[r1],       k01 = kp[256 + r1];
            float k10 = kp[r1 + 8],   k11 = kp[256 + r1 + 8];
            float q0 = qs[c], q1 = qs[c+1], b0v = bm[c], b1v = bm[c+1];
            float y00 = (acc1[mt][nt][0] + b0v) * q0 * k00;
            float y01 = (acc1[mt][nt][1] + b1v) * q1 * k01;
            float y10 = (acc1[mt][nt][2] + b0v) * q0 * k10;
            float y11 = (acc1[mt][nt][3] + b1v) * q1 * k11;
            __nv_bfloat16 h00,h01,h10,h11,l00,l01,l10,l11;
            split_bf16(y00,h00,l00); split_bf16(y01,h01,l01);
            split_bf16(y10,h10,l10); split_bf16(y11,h11,l11);
            uint32_t xr = (uint32_t)(g << 4);
            uint32_t a0 = (uint32_t)(r1*512)     + (((uint32_t)(2*c)) ^ xr);
            uint32_t a1 = (uint32_t)((r1+8)*512) + (((uint32_t)(2*c)) ^ xr);
            *(uint32_t*)(smem + YHI + a0) = pk_bf2(h00,h01);
            *(uint32_t*)(smem + YLO + a0) = pk_bf2(l00,l01);
            *(uint32_t*)(smem + YHI + a1) = pk_bf2(h10,h11);
            *(uint32_t*)(smem + YLO + a1) = pk_bf2(l10,l11);
        }
    }

    // ---- GEMM2: acc2 = [Y | e] @ [Weo; M2] (3-term split), pipelined --------
    float acc2[2][4][4];
#pragma unroll
    for (int mt = 0; mt < 2; mt++)
#pragma unroll
        for (int nt = 0; nt < 4; nt++)
#pragma unroll
            for (int v = 0; v < 4; v++) acc2[mt][nt][v] = 0.f;

    for (int s = 0; s < 12; s++) {
        CP_WAIT0();
        __syncthreads();
        if (s + 1 < 12) {
            const char* srcH = (const char*)(g_W2hi + (s+1)*5120);
            const char* srcL = (const char*)(g_W2lo + (s+1)*5120);
            uint32_t dH = sb + WBUF + ((s+1)&1)*20480, dL = dH + 10240;
            for (int i = tid*16; i < 10240; i += 256*16) {
                cp16(dH + i, srcH + i);
                cp16(dL + i, srcL + i);
            }
            CP_COMMIT();
        }
        const uint32_t wbase = sb + WBUF + (s & 1)*20480;
        const int isY = (s < 8);
        const uint32_t abase = isY ? (uint32_t)YHI : (uint32_t)EHI;
        const uint32_t dLO   = isY ? 32768u : 16384u;
        const int strideA    = isY ? 512 : 256;
        const int kbase      = isY ? s*32 : (s - 8)*32;
#pragma unroll
        for (int ks = 0; ks < 32; ks += 16) {
            uint32_t ah[2][4], al[2][4];
#pragma unroll
            for (int mt = 0; mt < 2; mt++) {
                int row = m0 + mt*16 + rA;
                uint32_t ad = sb + abase + (uint32_t)(row*strideA)
                            + (((uint32_t)(2*(kbase + ks + kAsel))) ^ xorA);
                ldm4(ah[mt], ad);
                ldm4(al[mt], ad + dLO);
            }
            uint32_t bh[4][2], bl[4][2];
#pragma unroll
            for (int p = 0; p < 2; p++) {
                int nrow = n0b + (2*p + bQn)*8 + rw;
                uint32_t ba = wbase + (uint32_t)(nrow*80) + (uint32_t)(2*ks) + bKoff;
                uint32_t t[4];
                ldm4(t, ba);
                bh[2*p][0]=t[0]; bh[2*p][1]=t[1]; bh[2*p+1][0]=t[2]; bh[2*p+1][1]=t[3];
                ldm4(t, ba + 10240);
                bl[2*p][0]=t[0]; bl[2*p][1]=t[1]; bl[2*p+1][0]=t[2]; bl[2*p+1][1]=t[3];
            }
#pragma unroll
            for (int mt = 0; mt < 2; mt++)
#pragma unroll
                for (int nt = 0; nt < 4; nt++) {
                    mma_bf(acc2[mt][nt], ah[mt], bh[nt]);
                    mma_bf(acc2[mt][nt], al[mt], bh[nt]);
                    mma_bf(acc2[mt][nt], ah[mt], bl[nt]);
                }
        }
    }

    // ---- store newE ----------------------------------------------------------
    float* outE = out + NEWX_ELEMS;
#pragma unroll
    for (int mt = 0; mt < 2; mt++) {
        int r1 = m0 + mt*16 + g;
#pragma unroll
        for (int nt = 0; nt < 4; nt++) {
            int c = n0b + nt*8 + 2*tg;
            float bo0 = bo[c], bo1 = bo[c+1];
            size_t row0 = (size_t)(bi*256 + j0 + r1);
            float2 v0 = make_float2(acc2[mt][nt][0] + bo0, acc2[mt][nt][1] + bo1);
            float2 v1 = make_float2(acc2[mt][nt][2] + bo0, acc2[mt][nt][3] + bo1);
            *(float2*)(outE + row0*128 + c)       = v0;
            *(float2*)(outE + (row0 + 8)*128 + c) = v1;
        }
    }
}

// ---------------- launch ------------------------------------------------------
extern "C" void kernel_launch(void* const* d_in, const int* in_sizes, int n_in,
                              void* d_out, int out_size) {
    const float* x   = (const float*)d_in[0];
    const float* e   = (const float*)d_in[1];
    const float* Wq  = (const float*)d_in[2];
    const float* bq  = (const float*)d_in[3];
    const float* Wk  = (const float*)d_in[4];
    const float* bk  = (const float*)d_in[5];
    const float* Wv  = (const float*)d_in[6];
    const float* bv  = (const float*)d_in[7];
    const float* Wem = (const float*)d_in[8];
    const float* bem = (const float*)d_in[9];
    const float* Wea = (const float*)d_in[10];
    const float* bea = (const float*)d_in[11];
    const float* Wxo = (const float*)d_in[12];
    const float* bxo = (const float*)d_in[13];
    const float* Weo = (const float*)d_in[14];
    const float* beo = (const float*)d_in[15];
    float* out = (float*)d_out;

    cudaFuncSetAttribute(k2_kernel, cudaFuncAttributeMaxDynamicSharedMemorySize, SMEM_BYTES);

    p0a_kernel<<<129, 256>>>(Wea, Weo, beo, bea, bem);
    p0b_kernel<<<64, 256>>>(Wem, Weo);
    p1_kernel<<<64, 256>>>(x, Wq, bq, Wk, bk, Wv, bv, Wxo, bxo, out);
    k2_kernel<<<4096, 256, SMEM_BYTES>>>(e, out);
}